// round 2
// baseline (speedup 1.0000x reference)
#include <cuda_runtime.h>
#include <math.h>

#define Bc   2
#define Cc   256
#define DMc  512
#define Hc   8
#define Dc   64
#define BHc  16
#define ROWS 4096   // B*H*C

typedef unsigned long long ULL;

// ---------------- f32x2 packed helpers ----------------
__device__ __forceinline__ void fma2(ULL& d, ULL a, ULL b) {
    asm("fma.rn.f32x2 %0, %1, %2, %0;" : "+l"(d) : "l"(a), "l"(b));
}
__device__ __forceinline__ ULL dup2(float x) {
    ULL d; asm("mov.b64 %0, {%1, %1};" : "=l"(d) : "f"(x)); return d;
}
__device__ __forceinline__ void unpack2(ULL v, float& x, float& y) {
    asm("mov.b64 {%0, %1}, %2;" : "=f"(x), "=f"(y) : "l"(v));
}
__device__ __forceinline__ float gelu_exact(float x) {
    return 0.5f * x * (1.0f + erff(x * 0.70710678118654752f));
}

// ---------------- device scratch ----------------
__device__ float g_q [ROWS * Dc];
__device__ float g_k [ROWS * Dc];
__device__ float g_v [ROWS * Dc];
__device__ float g_qp[ROWS * Dc];
__device__ float g_kp[ROWS * Dc];
__device__ float g_ctx[Bc * Cc * DMc];

// =====================================================================
// Generic 512x512x512 GEMM tile: out[m,e] = sum_d A[m,d]*W[e,d] + bias[e]
// 64x64 tile / block, 256 threads, 4m x 4n per thread (f32x2 along n).
// scatter=true -> write to [bh][c][d] head layout.
// =====================================================================
__device__ __forceinline__ void gemm512_tile(
    const float* __restrict__ A, const float* __restrict__ W,
    const float* __restrict__ bias, float* __restrict__ out, bool scatter)
{
    __shared__ float Xs[16][68];
    __shared__ float Wsh[16][68];
    int t  = threadIdx.x;
    int tx = t & 15, ty = t >> 4;
    int m0 = blockIdx.y * 64, n0 = blockIdx.x * 64;
    int lr = t >> 2, kq = (t & 3) * 4;

    ULL acc[4][2];
#pragma unroll
    for (int mm = 0; mm < 4; mm++) { acc[mm][0] = 0ULL; acc[mm][1] = 0ULL; }

    for (int kc = 0; kc < 512; kc += 16) {
        float4 xv = *(const float4*)(A + (size_t)(m0 + lr) * 512 + kc + kq);
        float4 wv = *(const float4*)(W + (size_t)(n0 + lr) * 512 + kc + kq);
        __syncthreads();
        Xs[kq + 0][lr] = xv.x; Xs[kq + 1][lr] = xv.y;
        Xs[kq + 2][lr] = xv.z; Xs[kq + 3][lr] = xv.w;
        Wsh[kq + 0][lr] = wv.x; Wsh[kq + 1][lr] = wv.y;
        Wsh[kq + 2][lr] = wv.z; Wsh[kq + 3][lr] = wv.w;
        __syncthreads();
#pragma unroll
        for (int kk = 0; kk < 16; kk++) {
            ulonglong2 wb = *(const ulonglong2*)&Wsh[kk][tx * 4];
#pragma unroll
            for (int mm = 0; mm < 4; mm++) {
                ULL ad = dup2(Xs[kk][ty * 4 + mm]);
                fma2(acc[mm][0], ad, wb.x);
                fma2(acc[mm][1], ad, wb.y);
            }
        }
    }

    int nb = n0 + tx * 4;
    float bb0 = bias[nb + 0], bb1 = bias[nb + 1];
    float bb2 = bias[nb + 2], bb3 = bias[nb + 3];
#pragma unroll
    for (int mm = 0; mm < 4; mm++) {
        int m = m0 + ty * 4 + mm;
        float f0, f1, f2, f3;
        unpack2(acc[mm][0], f0, f1);
        unpack2(acc[mm][1], f2, f3);
        f0 += bb0; f1 += bb1; f2 += bb2; f3 += bb3;
        if (scatter) {
            int b = m >> 8, c = m & 255;
            int h = nb >> 6, d0 = nb & 63;
            *(float4*)(out + ((size_t)((b * 8 + h) * 256 + c)) * 64 + d0) =
                make_float4(f0, f1, f2, f3);
        } else {
            *(float4*)(out + (size_t)m * 512 + nb) = make_float4(f0, f1, f2, f3);
        }
    }
}

__global__ __launch_bounds__(256) void qkv_kernel(
    const float* __restrict__ x,
    const float* __restrict__ Wq, const float* __restrict__ bq,
    const float* __restrict__ Wk, const float* __restrict__ bk,
    const float* __restrict__ Wv, const float* __restrict__ bv)
{
    int z = blockIdx.z;
    const float* W = (z == 0) ? Wq : (z == 1) ? Wk : Wv;
    const float* b = (z == 0) ? bq : (z == 1) ? bk : bv;
    float* out     = (z == 0) ? g_q : (z == 1) ? g_k : g_v;
    gemm512_tile(x, W, b, out, true);
}

__global__ __launch_bounds__(256) void outproj_kernel(
    const float* __restrict__ Wo, const float* __restrict__ bo,
    float* __restrict__ out)
{
    gemm512_tile(g_ctx, Wo, bo, out, false);
}

// =====================================================================
// q_p / k_p:  g_qp[r][e] = sum_d g_q[r][d]*w1[e][d]
//             g_kp[r][e] = sum_d g_k[r][d]*w1[e][64+d]
// =====================================================================
__global__ __launch_bounds__(256) void qpkp_kernel(const float* __restrict__ w1)
{
    __shared__ float w1T[2][64][68];   // [half][d][e]
    __shared__ float qrow[4][64];
    __shared__ float krow[4][64];
    int t = threadIdx.x;
    int r0 = blockIdx.x * 4;

#pragma unroll
    for (int it = 0; it < 8; it++) {
        int task = t + it * 256;
        int d4 = task & 15;
        int e  = (task >> 4) & 63;
        int half = task >> 10;
        float4 v = *(const float4*)(w1 + (size_t)e * 192 + half * 64 + d4 * 4);
        w1T[half][d4 * 4 + 0][e] = v.x;
        w1T[half][d4 * 4 + 1][e] = v.y;
        w1T[half][d4 * 4 + 2][e] = v.z;
        w1T[half][d4 * 4 + 3][e] = v.w;
    }
    {
        int rr = t >> 6, e = t & 63;
        qrow[rr][e] = g_q[(size_t)(r0 + rr) * 64 + e];
        krow[rr][e] = g_k[(size_t)(r0 + rr) * 64 + e];
    }
    __syncthreads();

    int rr = t >> 6, e = t & 63;
    float aq = 0.f, ak = 0.f;
#pragma unroll 8
    for (int d = 0; d < 64; d++) {
        aq += qrow[rr][d] * w1T[0][d][e];
        ak += krow[rr][d] * w1T[1][d][e];
    }
    g_qp[(size_t)(r0 + rr) * 64 + e] = aq;
    g_kp[(size_t)(r0 + rr) * 64 + e] = ak;
}

// =====================================================================
// Main fused kernel: bilinear scores + gelu/w2 + top-64 + softmax + attn*V
// Block: (bh, 8 i's as 4 pairs), 256 threads, dynamic smem.
// =====================================================================
// smem float offsets
#define KS_O    0        // [64][260]                66560 B
#define VS_O    16640    // [256][72]                73728 B
#define W3LO_O  35072    // [64][36]
#define W3HI_O  37376    // [64][36]
#define ALO_O   39680    // [2][64][36]
#define AHI_O   44288    // [2][64][36]
#define QPB_O   48896    // [2][64]
#define SC_O    49024    // [2][256]
#define RED_O   49536    // [64]
#define PART_O  49600    // [4][64]
#define SMEM_FLOATS 49856
#define SMEM_BYTES  (SMEM_FLOATS * 4)

__global__ __launch_bounds__(256, 1) void main_kernel(
    const float* __restrict__ w1, const float* __restrict__ b1,
    const float* __restrict__ w2, const float* __restrict__ b2)
{
    extern __shared__ float sm[];
    int t  = threadIdx.x;
    int bh = blockIdx.y;
    int i0 = blockIdx.x * 8;
    int base = bh * 256;

    // ---- load K (transposed, stride 260) and V (stride 72) ----
#pragma unroll
    for (int it = 0; it < 16; it++) {
        int task = t + it * 256;
        int eg = task & 15, j = task >> 4;
        float4 kv = *(const float4*)(g_k + (size_t)(base + j) * 64 + eg * 4);
        sm[KS_O + (eg * 4 + 0) * 260 + j] = kv.x;
        sm[KS_O + (eg * 4 + 1) * 260 + j] = kv.y;
        sm[KS_O + (eg * 4 + 2) * 260 + j] = kv.z;
        sm[KS_O + (eg * 4 + 3) * 260 + j] = kv.w;
        float4 vv = *(const float4*)(g_v + (size_t)(base + j) * 64 + eg * 4);
        *(float4*)&sm[VS_O + j * 72 + eg * 4] = vv;
    }
    // ---- load W3 split (lo: f%8<4, hi: f%8>=4), [e][fg*4+ff], stride 36 ----
#pragma unroll
    for (int it = 0; it < 16; it++) {
        int idx = t + it * 256;
        int e = idx & 63, f = idx >> 6;
        float val = w1[(size_t)f * 192 + 128 + e];
        int fg = f >> 3, ff = f & 7;
        if (ff < 4) sm[W3LO_O + e * 36 + fg * 4 + ff]       = val;
        else        sm[W3HI_O + e * 36 + fg * 4 + (ff - 4)] = val;
    }

    int jg = t >> 3, fg = t & 7;
    float w2r[8];
#pragma unroll
    for (int ff = 0; ff < 8; ff++) w2r[ff] = __ldg(&w2[fg * 8 + ff]);
    float b2v = __ldg(&b2[0]);

    for (int p = 0; p < 4; p++) {
        int ia = i0 + p * 2;
        __syncthreads();

        // qpb = q_p + b1 for the two i's
        if (t < 128) {
            int ii = t >> 6, f = t & 63;
            sm[QPB_O + ii * 64 + f] =
                g_qp[(size_t)(base + ia + ii) * 64 + f] + b1[f];
        }
        // build Ai (split layout): A[e][f'] = q_i[e] * W3split[e][f']
        {
            int sub = t >> 6;          // 0..3
            int ii  = sub >> 1;        // i of pair
            int half = sub & 1;        // 0=lo,1=hi
            int e = t & 63;
            float qv = g_q[(size_t)(base + ia + ii) * 64 + e];
            const float* src = sm + (half ? W3HI_O : W3LO_O) + e * 36;
            float* dst = sm + (half ? AHI_O : ALO_O) + ii * 2304 + e * 36;
#pragma unroll
            for (int x = 0; x < 32; x += 4) {
                float4 v = *(const float4*)(src + x);
                v.x *= qv; v.y *= qv; v.z *= qv; v.w *= qv;
                *(float4*)(dst + x) = v;
            }
        }
        __syncthreads();

        // ---- GEMM: M[i][j,f] = sum_e K[j,e]*Ai[e,f] ----
        ULL acc[2][8][4];
#pragma unroll
        for (int ii = 0; ii < 2; ii++)
#pragma unroll
            for (int jj = 0; jj < 8; jj++)
#pragma unroll
                for (int q = 0; q < 4; q++) acc[ii][jj][q] = 0ULL;

#pragma unroll 4
        for (int e = 0; e < 64; e++) {
            float4 k0 = *(const float4*)&sm[KS_O + e * 260 + jg * 8];
            float4 k1 = *(const float4*)&sm[KS_O + e * 260 + jg * 8 + 4];
            ulonglong2 a0l = *(const ulonglong2*)&sm[ALO_O + 0 * 2304 + e * 36 + fg * 4];
            ulonglong2 a0h = *(const ulonglong2*)&sm[AHI_O + 0 * 2304 + e * 36 + fg * 4];
            ulonglong2 a1l = *(const ulonglong2*)&sm[ALO_O + 1 * 2304 + e * 36 + fg * 4];
            ulonglong2 a1h = *(const ulonglong2*)&sm[AHI_O + 1 * 2304 + e * 36 + fg * 4];
            float kv[8] = {k0.x, k0.y, k0.z, k0.w, k1.x, k1.y, k1.z, k1.w};
#pragma unroll
            for (int jj = 0; jj < 8; jj++) {
                ULL kd = dup2(kv[jj]);
                fma2(acc[0][jj][0], kd, a0l.x);
                fma2(acc[0][jj][1], kd, a0l.y);
                fma2(acc[0][jj][2], kd, a0h.x);
                fma2(acc[0][jj][3], kd, a0h.y);
                fma2(acc[1][jj][0], kd, a1l.x);
                fma2(acc[1][jj][1], kd, a1l.y);
                fma2(acc[1][jj][2], kd, a1h.x);
                fma2(acc[1][jj][3], kd, a1h.y);
            }
        }

        // ---- epilogue: scores[i][j] = (sum_f gelu(res)*w2[f] + b2) / 8 ----
        float4 qa0 = *(const float4*)&sm[QPB_O + 0 * 64 + fg * 8];
        float4 qb0 = *(const float4*)&sm[QPB_O + 0 * 64 + fg * 8 + 4];
        float4 qa1 = *(const float4*)&sm[QPB_O + 1 * 64 + fg * 8];
        float4 qb1 = *(const float4*)&sm[QPB_O + 1 * 64 + fg * 8 + 4];

#pragma unroll
        for (int jj = 0; jj < 8; jj++) {
            int j = jg * 8 + jj;
            const float* kpp = g_kp + (size_t)(base + j) * 64 + fg * 8;
            float4 ka = *(const float4*)kpp;
            float4 kb = *(const float4*)(kpp + 4);
#pragma unroll
            for (int ii = 0; ii < 2; ii++) {
                float r0, r1, r2, r3, r4, r5, r6, r7;
                unpack2(acc[ii][jj][0], r0, r1);
                unpack2(acc[ii][jj][1], r2, r3);
                unpack2(acc[ii][jj][2], r4, r5);
                unpack2(acc[ii][jj][3], r6, r7);
                float4 qa = ii ? qa1 : qa0;
                float4 qb = ii ? qb1 : qb0;
                float s = 0.f;
                s += gelu_exact(r0 + qa.x + ka.x) * w2r[0];
                s += gelu_exact(r1 + qa.y + ka.y) * w2r[1];
                s += gelu_exact(r2 + qa.z + ka.z) * w2r[2];
                s += gelu_exact(r3 + qa.w + ka.w) * w2r[3];
                s += gelu_exact(r4 + qb.x + kb.x) * w2r[4];
                s += gelu_exact(r5 + qb.y + kb.y) * w2r[5];
                s += gelu_exact(r6 + qb.z + kb.z) * w2r[6];
                s += gelu_exact(r7 + qb.w + kb.w) * w2r[7];
                s += __shfl_xor_sync(0xffffffffu, s, 1);
                s += __shfl_xor_sync(0xffffffffu, s, 2);
                s += __shfl_xor_sync(0xffffffffu, s, 4);
                if (fg == 0) sm[SC_O + ii * 256 + j] = (s + b2v) * 0.125f;
            }
        }
        __syncthreads();

        // ---- per-i: top-64 threshold, softmax, attn @ V ----
#pragma unroll
        for (int ii = 0; ii < 2; ii++) {
            float v = sm[SC_O + ii * 256 + t];

            // block max
            float m = v;
            m = fmaxf(m, __shfl_xor_sync(0xffffffffu, m, 16));
            m = fmaxf(m, __shfl_xor_sync(0xffffffffu, m, 8));
            m = fmaxf(m, __shfl_xor_sync(0xffffffffu, m, 4));
            m = fmaxf(m, __shfl_xor_sync(0xffffffffu, m, 2));
            m = fmaxf(m, __shfl_xor_sync(0xffffffffu, m, 1));
            if ((t & 31) == 0) sm[RED_O + (t >> 5)] = m;
            __syncthreads();
            float mx = sm[RED_O + 0];
#pragma unroll
            for (int w = 1; w < 8; w++) mx = fmaxf(mx, sm[RED_O + w]);

            // rank counts -> 64th-largest threshold
            int cg = 0, ce = 0;
            const float* scp = sm + SC_O + ii * 256;
#pragma unroll 8
            for (int jt = 0; jt < 64; jt++) {
                float4 s4 = *(const float4*)(scp + jt * 4);
                cg += (s4.x > v) + (s4.y > v) + (s4.z > v) + (s4.w > v);
                ce += (s4.x == v) + (s4.y == v) + (s4.z == v) + (s4.w == v);
            }
            if (cg <= 63 && cg + ce >= 64) sm[RED_O + 8] = v;
            __syncthreads();
            float thr = sm[RED_O + 8];

            float ev = (v >= thr) ? expf(v - mx) : 0.f;
            float ssum = ev;
            ssum += __shfl_xor_sync(0xffffffffu, ssum, 16);
            ssum += __shfl_xor_sync(0xffffffffu, ssum, 8);
            ssum += __shfl_xor_sync(0xffffffffu, ssum, 4);
            ssum += __shfl_xor_sync(0xffffffffu, ssum, 2);
            ssum += __shfl_xor_sync(0xffffffffu, ssum, 1);
            if ((t & 31) == 0) sm[RED_O + 16 + (t >> 5)] = ssum;
            __syncthreads();
            float den = 0.f;
#pragma unroll
            for (int w = 0; w < 8; w++) den += sm[RED_O + 16 + w];
            float attn = ev / den;
            sm[SC_O + ii * 256 + t] = attn;
            __syncthreads();

            // attn @ V
            int g = t >> 6, d = t & 63;
            float a = 0.f;
            const float* ap = sm + SC_O + ii * 256 + g * 64;
            const float* vp = sm + VS_O + g * 64 * 72 + d;
#pragma unroll 8
            for (int j = 0; j < 64; j++) a += ap[j] * vp[j * 72];
            sm[PART_O + g * 64 + d] = a;
            __syncthreads();
            if (t < 64) {
                float o = sm[PART_O + t] + sm[PART_O + 64 + t] +
                          sm[PART_O + 128 + t] + sm[PART_O + 192 + t];
                int irow = ia + ii;
                g_ctx[(size_t)((bh >> 3) * 256 + irow) * 512 + (bh & 7) * 64 + t] = o;
            }
            __syncthreads();
        }
    }
}

// =====================================================================
extern "C" void kernel_launch(void* const* d_in, const int* in_sizes, int n_in,
                              void* d_out, int out_size)
{
    const float* x  = (const float*)d_in[0];
    const float* Wq = (const float*)d_in[1];
    const float* bq = (const float*)d_in[2];
    const float* Wk = (const float*)d_in[3];
    const float* bk = (const float*)d_in[4];
    const float* Wv = (const float*)d_in[5];
    const float* bv = (const float*)d_in[6];
    const float* w1 = (const float*)d_in[7];
    const float* b1 = (const float*)d_in[8];
    const float* w2 = (const float*)d_in[9];
    const float* b2 = (const float*)d_in[10];
    const float* Wo = (const float*)d_in[11];
    const float* bo = (const float*)d_in[12];
    float* out = (float*)d_out;

    cudaFuncSetAttribute(main_kernel,
                         cudaFuncAttributeMaxDynamicSharedMemorySize, SMEM_BYTES);

    qkv_kernel<<<dim3(8, 8, 3), 256>>>(x, Wq, bq, Wk, bk, Wv, bv);
    qpkp_kernel<<<1024, 256>>>(w1);
    main_kernel<<<dim3(32, 16), 256, SMEM_BYTES>>>(w1, b1, w2, b2);
    outproj_kernel<<<dim3(8, 8), 256>>>(Wo, bo, out);
}

// round 3
// speedup vs baseline: 1.0291x; 1.0291x over previous
#include <cuda_runtime.h>
#include <math.h>

#define Bc   2
#define Cc   256
#define DMc  512
#define Hc   8
#define Dc   64
#define BHc  16
#define ROWS 4096   // B*H*C

typedef unsigned long long ULL;

// ---------------- f32x2 packed helpers ----------------
__device__ __forceinline__ void fma2(ULL& d, ULL a, ULL b) {
    asm("fma.rn.f32x2 %0, %1, %2, %0;" : "+l"(d) : "l"(a), "l"(b));
}
__device__ __forceinline__ ULL dup2(float x) {
    ULL d; asm("mov.b64 %0, {%1, %1};" : "=l"(d) : "f"(x)); return d;
}
__device__ __forceinline__ void unpack2(ULL v, float& x, float& y) {
    asm("mov.b64 {%0, %1}, %2;" : "=f"(x), "=f"(y) : "l"(v));
}

// Branchless gelu: A&S 7.1.26 erf (|err| <= 1.5e-7), rcp.approx + ex2.approx.
__device__ __forceinline__ float fast_gelu(float x) {
    float y  = x * 0.70710678118654752f;
    float ay = fabsf(y);
    float den = fmaf(0.3275911f, ay, 1.0f);
    float t;
    asm("rcp.approx.f32 %0, %1;" : "=f"(t) : "f"(den));
    float p = fmaf(1.061405429f, t, -1.453152027f);
    p = fmaf(p, t, 1.421413741f);
    p = fmaf(p, t, -0.284496736f);
    p = fmaf(p, t, 0.254829592f);
    p *= t;
    float e = __expf(-ay * ay);
    float erfv = fmaf(-p, e, 1.0f);
    erfv = copysignf(erfv, y);
    return 0.5f * x * (1.0f + erfv);
}

// ---------------- device scratch ----------------
__device__ float g_q [ROWS * Dc];
__device__ float g_k [ROWS * Dc];
__device__ float g_v [ROWS * Dc];
__device__ float g_qp[ROWS * Dc];
__device__ float g_kp[ROWS * Dc];
__device__ float g_ctx[Bc * Cc * DMc];

// =====================================================================
// GEMM: out[m,e] = sum_d A[m,d]*W[e,d] + bias[e]   (K = 512)
// Tile TM x 64, 256 threads, register double-buffered global loads.
// thread tile (TM/16) m  x  4 n  (f32x2 pairs along n).
// =====================================================================
template<int TM>
__device__ __forceinline__ void gemm512(
    const float* __restrict__ A, const float* __restrict__ W,
    const float* __restrict__ bias, float* __restrict__ out, bool scatter,
    int m0, int n0)
{
    __shared__ float Xs[16][TM + 4];
    __shared__ float Wsh[16][68];
    constexpr int MT = TM / 16;
    int t  = threadIdx.x;
    int tx = t & 15, ty = t >> 4;
    int lr = t >> 2, kq = (t & 3) * 4;
    bool xload = (t < TM * 4);

    ULL acc[MT][2];
#pragma unroll
    for (int mm = 0; mm < MT; mm++) { acc[mm][0] = 0ULL; acc[mm][1] = 0ULL; }

    float4 xv, wv;
    if (xload) xv = *(const float4*)(A + (size_t)(m0 + lr) * 512 + kq);
    wv = *(const float4*)(W + (size_t)(n0 + lr) * 512 + kq);

    for (int kc = 0; kc < 512; kc += 16) {
        if (kc) __syncthreads();
        if (xload) {
            Xs[kq + 0][lr] = xv.x; Xs[kq + 1][lr] = xv.y;
            Xs[kq + 2][lr] = xv.z; Xs[kq + 3][lr] = xv.w;
        }
        Wsh[kq + 0][lr] = wv.x; Wsh[kq + 1][lr] = wv.y;
        Wsh[kq + 2][lr] = wv.z; Wsh[kq + 3][lr] = wv.w;
        __syncthreads();
        if (kc + 16 < 512) {
            if (xload) xv = *(const float4*)(A + (size_t)(m0 + lr) * 512 + kc + 16 + kq);
            wv = *(const float4*)(W + (size_t)(n0 + lr) * 512 + kc + 16 + kq);
        }
#pragma unroll
        for (int kk = 0; kk < 16; kk++) {
            ulonglong2 wb = *(const ulonglong2*)&Wsh[kk][tx * 4];
#pragma unroll
            for (int mm = 0; mm < MT; mm++) {
                ULL ad = dup2(Xs[kk][ty * MT + mm]);
                fma2(acc[mm][0], ad, wb.x);
                fma2(acc[mm][1], ad, wb.y);
            }
        }
    }

    int nb = n0 + tx * 4;
    float bb0 = bias[nb + 0], bb1 = bias[nb + 1];
    float bb2 = bias[nb + 2], bb3 = bias[nb + 3];
#pragma unroll
    for (int mm = 0; mm < MT; mm++) {
        int m = m0 + ty * MT + mm;
        float f0, f1, f2, f3;
        unpack2(acc[mm][0], f0, f1);
        unpack2(acc[mm][1], f2, f3);
        f0 += bb0; f1 += bb1; f2 += bb2; f3 += bb3;
        if (scatter) {
            int b = m >> 8, c = m & 255;
            int h = nb >> 6, d0 = nb & 63;
            *(float4*)(out + ((size_t)((b * 8 + h) * 256 + c)) * 64 + d0) =
                make_float4(f0, f1, f2, f3);
        } else {
            *(float4*)(out + (size_t)m * 512 + nb) = make_float4(f0, f1, f2, f3);
        }
    }
}

__global__ __launch_bounds__(256) void qkv_kernel(
    const float* __restrict__ x,
    const float* __restrict__ Wq, const float* __restrict__ bq,
    const float* __restrict__ Wk, const float* __restrict__ bk,
    const float* __restrict__ Wv, const float* __restrict__ bv)
{
    int z = blockIdx.z;
    const float* W = (z == 0) ? Wq : (z == 1) ? Wk : Wv;
    const float* b = (z == 0) ? bq : (z == 1) ? bk : bv;
    float* out     = (z == 0) ? g_q : (z == 1) ? g_k : g_v;
    gemm512<64>(x, W, b, out, true, blockIdx.y * 64, blockIdx.x * 64);
}

__global__ __launch_bounds__(256) void outproj_kernel(
    const float* __restrict__ Wo, const float* __restrict__ bo,
    float* __restrict__ out)
{
    gemm512<32>(g_ctx, Wo, bo, out, false, blockIdx.y * 32, blockIdx.x * 64);
}

// =====================================================================
// q_p / k_p: 8 rows per block (amortize w1 staging)
// =====================================================================
__global__ __launch_bounds__(256) void qpkp_kernel(const float* __restrict__ w1)
{
    __shared__ float w1T[2][64][68];   // [half][d][e]
    __shared__ float qrow[4][64];
    __shared__ float krow[4][64];
    int t = threadIdx.x;
    int r0 = blockIdx.x * 8;

#pragma unroll
    for (int it = 0; it < 8; it++) {
        int task = t + it * 256;
        int d4 = task & 15;
        int e  = (task >> 4) & 63;
        int half = task >> 10;
        float4 v = *(const float4*)(w1 + (size_t)e * 192 + half * 64 + d4 * 4);
        w1T[half][d4 * 4 + 0][e] = v.x;
        w1T[half][d4 * 4 + 1][e] = v.y;
        w1T[half][d4 * 4 + 2][e] = v.z;
        w1T[half][d4 * 4 + 3][e] = v.w;
    }

    int rr = t >> 6, e = t & 63;
#pragma unroll
    for (int rep = 0; rep < 2; rep++) {
        int rb = r0 + rep * 4;
        __syncthreads();
        qrow[rr][e] = g_q[(size_t)(rb + rr) * 64 + e];
        krow[rr][e] = g_k[(size_t)(rb + rr) * 64 + e];
        __syncthreads();
        float aq = 0.f, ak = 0.f;
#pragma unroll 8
        for (int d = 0; d < 64; d++) {
            aq = fmaf(qrow[rr][d], w1T[0][d][e], aq);
            ak = fmaf(krow[rr][d], w1T[1][d][e], ak);
        }
        g_qp[(size_t)(rb + rr) * 64 + e] = aq;
        g_kp[(size_t)(rb + rr) * 64 + e] = ak;
    }
}

// =====================================================================
// Main fused kernel. Block = (bh, 4 i's as 2 pairs), 256 threads.
// =====================================================================
#define KS_O    0        // [64][260]
#define VS_O    16640    // [256][72]
#define W3LO_O  35072    // [64][36]
#define W3HI_O  37376    // [64][36]
#define ALO_O   39680    // [2][64][36]
#define AHI_O   44288    // [2][64][36]
#define QPB_O   48896    // [2][64]
#define SC_O    49024    // [2][256]
#define RED_O   49536    // [64]
#define PART_O  49600    // [4][64]
#define PART2_O 49856    // [4][64]
#define SMEM_FLOATS 50112
#define SMEM_BYTES  (SMEM_FLOATS * 4)

__global__ __launch_bounds__(256, 1) void main_kernel(
    const float* __restrict__ w1, const float* __restrict__ b1,
    const float* __restrict__ w2, const float* __restrict__ b2)
{
    extern __shared__ float sm[];
    int t  = threadIdx.x;
    int bh = blockIdx.y;
    int i0 = blockIdx.x * 4;
    int base = bh * 256;
    int jg = t >> 3, fg = t & 7;

    // ---- hoisted k_p registers (i-independent!) ----
    float4 kpa[8], kpb[8];
#pragma unroll
    for (int jj = 0; jj < 8; jj++) {
        const float* kpp = g_kp + (size_t)(base + jg * 8 + jj) * 64 + fg * 8;
        kpa[jj] = *(const float4*)kpp;
        kpb[jj] = *(const float4*)(kpp + 4);
    }
    float w2r[8];
#pragma unroll
    for (int ff = 0; ff < 8; ff++) w2r[ff] = __ldg(&w2[fg * 8 + ff]);
    float b2v = __ldg(&b2[0]);

    // ---- load K (transposed, stride 260) and V (stride 72) ----
#pragma unroll
    for (int it = 0; it < 16; it++) {
        int task = t + it * 256;
        int eg = task & 15, j = task >> 4;
        float4 kv = *(const float4*)(g_k + (size_t)(base + j) * 64 + eg * 4);
        sm[KS_O + (eg * 4 + 0) * 260 + j] = kv.x;
        sm[KS_O + (eg * 4 + 1) * 260 + j] = kv.y;
        sm[KS_O + (eg * 4 + 2) * 260 + j] = kv.z;
        sm[KS_O + (eg * 4 + 3) * 260 + j] = kv.w;
        float4 vv = *(const float4*)(g_v + (size_t)(base + j) * 64 + eg * 4);
        *(float4*)&sm[VS_O + j * 72 + eg * 4] = vv;
    }
    // ---- W3 split (lo: f%8<4, hi: f%8>=4) ----
#pragma unroll
    for (int it = 0; it < 16; it++) {
        int idx = t + it * 256;
        int e = idx & 63, f = idx >> 6;
        float val = w1[(size_t)f * 192 + 128 + e];
        int fgr = f >> 3, ff = f & 7;
        if (ff < 4) sm[W3LO_O + e * 36 + fgr * 4 + ff]       = val;
        else        sm[W3HI_O + e * 36 + fgr * 4 + (ff - 4)] = val;
    }

#pragma unroll 1
    for (int p = 0; p < 2; p++) {
        int ia = i0 + p * 2;
        __syncthreads();

        if (t < 128) {
            int ii = t >> 6, f = t & 63;
            sm[QPB_O + ii * 64 + f] =
                g_qp[(size_t)(base + ia + ii) * 64 + f] + b1[f];
        }
        {
            int sub = t >> 6;
            int ii  = sub >> 1;
            int half = sub & 1;
            int e = t & 63;
            float qv = g_q[(size_t)(base + ia + ii) * 64 + e];
            const float* src = sm + (half ? W3HI_O : W3LO_O) + e * 36;
            float* dst = sm + (half ? AHI_O : ALO_O) + ii * 2304 + e * 36;
#pragma unroll
            for (int x = 0; x < 32; x += 4) {
                float4 v = *(const float4*)(src + x);
                v.x *= qv; v.y *= qv; v.z *= qv; v.w *= qv;
                *(float4*)(dst + x) = v;
            }
        }
        __syncthreads();

        // ---- GEMM: M[i][j,f] = sum_e K[j,e]*Ai[e,f] ----
        ULL acc[2][8][4];
#pragma unroll
        for (int ii = 0; ii < 2; ii++)
#pragma unroll
            for (int jj = 0; jj < 8; jj++)
#pragma unroll
                for (int q = 0; q < 4; q++) acc[ii][jj][q] = 0ULL;

#pragma unroll 2
        for (int e = 0; e < 64; e++) {
            float4 k0 = *(const float4*)&sm[KS_O + e * 260 + jg * 8];
            float4 k1 = *(const float4*)&sm[KS_O + e * 260 + jg * 8 + 4];
            ulonglong2 a0l = *(const ulonglong2*)&sm[ALO_O + 0 * 2304 + e * 36 + fg * 4];
            ulonglong2 a0h = *(const ulonglong2*)&sm[AHI_O + 0 * 2304 + e * 36 + fg * 4];
            ulonglong2 a1l = *(const ulonglong2*)&sm[ALO_O + 1 * 2304 + e * 36 + fg * 4];
            ulonglong2 a1h = *(const ulonglong2*)&sm[AHI_O + 1 * 2304 + e * 36 + fg * 4];
            float kv[8] = {k0.x, k0.y, k0.z, k0.w, k1.x, k1.y, k1.z, k1.w};
#pragma unroll
            for (int jj = 0; jj < 8; jj++) {
                ULL kd = dup2(kv[jj]);
                fma2(acc[0][jj][0], kd, a0l.x);
                fma2(acc[0][jj][1], kd, a0l.y);
                fma2(acc[0][jj][2], kd, a0h.x);
                fma2(acc[0][jj][3], kd, a0h.y);
                fma2(acc[1][jj][0], kd, a1l.x);
                fma2(acc[1][jj][1], kd, a1l.y);
                fma2(acc[1][jj][2], kd, a1h.x);
                fma2(acc[1][jj][3], kd, a1h.y);
            }
        }

        // ---- epilogue: scores = (sum_f gelu(res)*w2[f] + b2) / 8 ----
        float4 qa0 = *(const float4*)&sm[QPB_O + 0 * 64 + fg * 8];
        float4 qb0 = *(const float4*)&sm[QPB_O + 0 * 64 + fg * 8 + 4];
        float4 qa1 = *(const float4*)&sm[QPB_O + 1 * 64 + fg * 8];
        float4 qb1 = *(const float4*)&sm[QPB_O + 1 * 64 + fg * 8 + 4];

#pragma unroll
        for (int jj = 0; jj < 8; jj++) {
            int j = jg * 8 + jj;
            float4 ka = kpa[jj], kb = kpb[jj];
#pragma unroll
            for (int ii = 0; ii < 2; ii++) {
                float r0, r1, r2, r3, r4, r5, r6, r7;
                unpack2(acc[ii][jj][0], r0, r1);
                unpack2(acc[ii][jj][1], r2, r3);
                unpack2(acc[ii][jj][2], r4, r5);
                unpack2(acc[ii][jj][3], r6, r7);
                float4 qa = ii ? qa1 : qa0;
                float4 qb = ii ? qb1 : qb0;
                float s = 0.f;
                s = fmaf(fast_gelu(r0 + qa.x + ka.x), w2r[0], s);
                s = fmaf(fast_gelu(r1 + qa.y + ka.y), w2r[1], s);
                s = fmaf(fast_gelu(r2 + qa.z + ka.z), w2r[2], s);
                s = fmaf(fast_gelu(r3 + qa.w + ka.w), w2r[3], s);
                s = fmaf(fast_gelu(r4 + qb.x + kb.x), w2r[4], s);
                s = fmaf(fast_gelu(r5 + qb.y + kb.y), w2r[5], s);
                s = fmaf(fast_gelu(r6 + qb.z + kb.z), w2r[6], s);
                s = fmaf(fast_gelu(r7 + qb.w + kb.w), w2r[7], s);
                s += __shfl_xor_sync(0xffffffffu, s, 1);
                s += __shfl_xor_sync(0xffffffffu, s, 2);
                s += __shfl_xor_sync(0xffffffffu, s, 4);
                if (fg == 0) sm[SC_O + ii * 256 + j] = (s + b2v) * 0.125f;
            }
        }
        __syncthreads();

        // ---- fused tail for both i's: top-64, softmax, attn@V ----
        float v0 = sm[SC_O + t];
        float v1 = sm[SC_O + 256 + t];
        float m0 = v0, m1 = v1;
#pragma unroll
        for (int o = 16; o; o >>= 1) {
            m0 = fmaxf(m0, __shfl_xor_sync(0xffffffffu, m0, o));
            m1 = fmaxf(m1, __shfl_xor_sync(0xffffffffu, m1, o));
        }
        if ((t & 31) == 0) {
            sm[RED_O + (t >> 5)]     = m0;
            sm[RED_O + 8 + (t >> 5)] = m1;
        }
        __syncthreads();
        float mx0 = sm[RED_O], mx1 = sm[RED_O + 8];
#pragma unroll
        for (int w = 1; w < 8; w++) {
            mx0 = fmaxf(mx0, sm[RED_O + w]);
            mx1 = fmaxf(mx1, sm[RED_O + 8 + w]);
        }

        int cg0 = 0, ce0 = 0, cg1 = 0, ce1 = 0;
        const float* sc0 = sm + SC_O;
        const float* sc1 = sm + SC_O + 256;
#pragma unroll 4
        for (int jt = 0; jt < 64; jt++) {
            float4 a = *(const float4*)(sc0 + jt * 4);
            float4 b = *(const float4*)(sc1 + jt * 4);
            cg0 += (a.x > v0) + (a.y > v0) + (a.z > v0) + (a.w > v0);
            ce0 += (a.x == v0) + (a.y == v0) + (a.z == v0) + (a.w == v0);
            cg1 += (b.x > v1) + (b.y > v1) + (b.z > v1) + (b.w > v1);
            ce1 += (b.x == v1) + (b.y == v1) + (b.z == v1) + (b.w == v1);
        }
        if (cg0 <= 63 && cg0 + ce0 >= 64) sm[RED_O + 16] = v0;
        if (cg1 <= 63 && cg1 + ce1 >= 64) sm[RED_O + 17] = v1;
        __syncthreads();
        float thr0 = sm[RED_O + 16], thr1 = sm[RED_O + 17];

        float e0 = (v0 >= thr0) ? __expf(v0 - mx0) : 0.f;
        float e1 = (v1 >= thr1) ? __expf(v1 - mx1) : 0.f;
        float s0 = e0, s1 = e1;
#pragma unroll
        for (int o = 16; o; o >>= 1) {
            s0 += __shfl_xor_sync(0xffffffffu, s0, o);
            s1 += __shfl_xor_sync(0xffffffffu, s1, o);
        }
        if ((t & 31) == 0) {
            sm[RED_O + 24 + (t >> 5)] = s0;
            sm[RED_O + 32 + (t >> 5)] = s1;
        }
        __syncthreads();
        float den0 = 0.f, den1 = 0.f;
#pragma unroll
        for (int w = 0; w < 8; w++) {
            den0 += sm[RED_O + 24 + w];
            den1 += sm[RED_O + 32 + w];
        }
        sm[SC_O + t]       = e0 / den0;
        sm[SC_O + 256 + t] = e1 / den1;
        __syncthreads();

        // attn @ V for both i's (shared V loads)
        {
            int g = t >> 6, d = t & 63;
            float a0 = 0.f, a1 = 0.f;
            const float* ap0 = sm + SC_O + g * 64;
            const float* ap1 = sm + SC_O + 256 + g * 64;
            const float* vp  = sm + VS_O + g * 64 * 72 + d;
#pragma unroll 8
            for (int j = 0; j < 64; j++) {
                float vv = vp[j * 72];
                a0 = fmaf(ap0[j], vv, a0);
                a1 = fmaf(ap1[j], vv, a1);
            }
            sm[PART_O  + g * 64 + d] = a0;
            sm[PART2_O + g * 64 + d] = a1;
        }
        __syncthreads();
        if (t < 128) {
            int ii = t >> 6, dd = t & 63;
            const float* pb = sm + (ii ? PART2_O : PART_O);
            float o = pb[dd] + pb[64 + dd] + pb[128 + dd] + pb[192 + dd];
            int irow = ia + ii;
            g_ctx[(size_t)((bh >> 3) * 256 + irow) * 512 + (bh & 7) * 64 + dd] = o;
        }
    }
}

// =====================================================================
extern "C" void kernel_launch(void* const* d_in, const int* in_sizes, int n_in,
                              void* d_out, int out_size)
{
    const float* x  = (const float*)d_in[0];
    const float* Wq = (const float*)d_in[1];
    const float* bq = (const float*)d_in[2];
    const float* Wk = (const float*)d_in[3];
    const float* bk = (const float*)d_in[4];
    const float* Wv = (const float*)d_in[5];
    const float* bv = (const float*)d_in[6];
    const float* w1 = (const float*)d_in[7];
    const float* b1 = (const float*)d_in[8];
    const float* w2 = (const float*)d_in[9];
    const float* b2 = (const float*)d_in[10];
    const float* Wo = (const float*)d_in[11];
    const float* bo = (const float*)d_in[12];
    float* out = (float*)d_out;

    cudaFuncSetAttribute(main_kernel,
                         cudaFuncAttributeMaxDynamicSharedMemorySize, SMEM_BYTES);

    qkv_kernel<<<dim3(8, 8, 3), 256>>>(x, Wq, bq, Wk, bk, Wv, bv);
    qpkp_kernel<<<512, 256>>>(w1);
    main_kernel<<<dim3(64, 16), 256, SMEM_BYTES>>>(w1, b1, w2, b2);
    outproj_kernel<<<dim3(8, 16), 256>>>(Wo, bo, out);
}